// round 10
// baseline (speedup 1.0000x reference)
#include <cuda_runtime.h>
#include <cstdint>

#define N_PTS  1000000
#define KNN    9
#define C      20
#define CIN3   23
#define TPB    256
#define RST    20                               // compact row stride (floats) = 80B
#define PPBG   32                               // points per block (gather kernels)
#define NBLKG  (N_PTS / PPBG)                   // 31250 (exact)
#define NBLKR  ((N_PTS + TPB - 1) / TPB)        // 3907
#define PARTN  NBLKG
#define EPSV   1e-5f
#define FULLM  0xffffffffu

// ---------------- scratch (device globals; allocation-free) -----------------
__device__ __align__(16) float g_G0[(size_t)N_PTS * RST];  // conv precompute (80MB)
__device__ __align__(16) float g_v [(size_t)N_PTS * RST];  // first aggregation (80MB)
__device__ __align__(16) float g_x2[N_PTS * C];            // second aggregation
__device__ __align__(16) float g_h [N_PTS * C];            // pre-BN3 linear output
__device__ __align__(16) int   g_idx[N_PTS * KNN];         // int32 index copy (36MB)
__device__ float g_wgt[N_PTS * KNN];
__device__ float g_part_t[40 * PARTN];
__device__ float g_scale[C];
__device__ float g_bias[C];
__device__ int   g_idx64;
__device__ int   g_arrive;

// ---------------- helpers ---------------------------------------------------
__device__ __forceinline__ void load20(float* r, const float* p) {
    const float4* q = (const float4*)p;
#pragma unroll
    for (int i = 0; i < 5; i++) {
        float4 t = q[i];
        r[4*i] = t.x; r[4*i+1] = t.y; r[4*i+2] = t.z; r[4*i+3] = t.w;
    }
}
// L2 evict-last access policy (legal encoding: createpolicy + cache_hint)
__device__ __forceinline__ uint64_t evl_policy() {
    uint64_t pol;
    asm("createpolicy.fractional.L2::evict_last.b64 %0, 1.0;" : "=l"(pol));
    return pol;
}
// gather load with evict-last policy
__device__ __forceinline__ float4 ldg_evl(const float* p, uint64_t pol) {
    float4 r;
    asm volatile("ld.global.nc.L2::cache_hint.v4.f32 {%0,%1,%2,%3}, [%4], %5;"
                 : "=f"(r.x), "=f"(r.y), "=f"(r.z), "=f"(r.w)
                 : "l"(p), "l"(pol));
    return r;
}
__device__ __forceinline__ float grp8_sum(float v) {
    v += __shfl_xor_sync(FULLM, v, 1);
    v += __shfl_xor_sync(FULLM, v, 2);
    v += __shfl_xor_sync(FULLM, v, 4);
    return v;
}

// last-arriving block reduces g_part_t and folds BN into g_scale/g_bias
__device__ void fold_tail(int nblk, const float* __restrict__ g,
                          const float* __restrict__ b, float inv_count) {
    __shared__ int s_last;
    __threadfence();
    __syncthreads();
    if (threadIdx.x == 0) {
        int prev = atomicAdd(&g_arrive, 1);
        s_last = (prev == nblk - 1) ? 1 : 0;
    }
    __syncthreads();
    if (!s_last) return;
    __threadfence();
    int lane = threadIdx.x & 31, warp = threadIdx.x >> 5;
    __shared__ float tot[40];
#pragma unroll
    for (int si = 0; si < 5; si++) {
        int slot = warp + si * 8;
        const float* pp = g_part_t + slot * PARTN;
        float a0 = 0.f, a1 = 0.f, a2 = 0.f, a3 = 0.f;
        int i = lane;
        for (; i + 96 < nblk; i += 128) {
            a0 += pp[i]; a1 += pp[i+32]; a2 += pp[i+64]; a3 += pp[i+96];
        }
        for (; i < nblk; i += 32) a0 += pp[i];
        float a = (a0 + a1) + (a2 + a3);
#pragma unroll
        for (int off = 16; off > 0; off >>= 1) a += __shfl_xor_sync(FULLM, a, off);
        if (lane == 0) tot[slot] = a;
    }
    __syncthreads();
    if (threadIdx.x < C) {
        int o = threadIdx.x;
        float mean = tot[o] * inv_count;
        float var  = fmaf(-mean, mean, tot[20 + o] * inv_count);
        float x = var + EPSV;
        float r = rsqrtf(x);
        r = r * (1.5f - 0.5f * x * r * r);
        float sc = g[o] * r;
        g_scale[o] = sc;
        g_bias[o]  = b[o] - mean * sc;
    }
    if (threadIdx.x == 0) g_arrive = 0;
}

// per-lane stats (4 channels each; lanes l<5 of each 8-lane group hold data)
__device__ __forceinline__ void lane_stats_store(float* s, float* q, int blk) {
    int lane = threadIdx.x & 31, warp = threadIdx.x >> 5;
#pragma unroll
    for (int i = 0; i < 4; i++) {
        s[i] += __shfl_down_sync(FULLM, s[i], 16);
        s[i] += __shfl_down_sync(FULLM, s[i], 8);
        q[i] += __shfl_down_sync(FULLM, q[i], 16);
        q[i] += __shfl_down_sync(FULLM, q[i], 8);
    }
    __shared__ float sh[8][40];
    if (lane < 5) {
#pragma unroll
        for (int i = 0; i < 4; i++) {
            sh[warp][4*lane + i]      = s[i];
            sh[warp][20 + 4*lane + i] = q[i];
        }
    }
    __syncthreads();
    if (threadIdx.x < 40) {
        float a = 0.f;
#pragma unroll
        for (int w = 0; w < 8; w++) a += sh[w][threadIdx.x];
        g_part_t[threadIdx.x * PARTN + blk] = a;
    }
}

// per-thread stats (all 20 channels) -> block partials (refine kernel)
__device__ __forceinline__ void stats_reduce_store(float* s, float* q, int blk) {
#pragma unroll
    for (int o = 0; o < C; o++) {
#pragma unroll
        for (int off = 16; off > 0; off >>= 1) {
            s[o] += __shfl_down_sync(FULLM, s[o], off);
            q[o] += __shfl_down_sync(FULLM, q[o], off);
        }
    }
    __shared__ float sh[8][40];
    int warp = threadIdx.x >> 5, lane = threadIdx.x & 31;
    if (lane == 0) {
#pragma unroll
        for (int o = 0; o < C; o++) { sh[warp][o] = s[o]; sh[warp][20+o] = q[o]; }
    }
    __syncthreads();
    if (threadIdx.x < 40) {
        float a = 0.f;
#pragma unroll
        for (int w = 0; w < 8; w++) a += sh[w][threadIdx.x];
        g_part_t[threadIdx.x * PARTN + blk] = a;
    }
}

// ---------------- kernels ---------------------------------------------------

__global__ void k_detect(const void* idx) {
    if (threadIdx.x == 0) {
        const int* p = (const int*)idx;
        int odd_zero = 1;
        for (int i = 0; i < 64; i++)
            if (p[2 * i + 1] != 0) odd_zero = 0;
        g_idx64 = odd_zero;
    }
}

// convert index to int32 once (evict-first both sides)
__global__ void __launch_bounds__(TPB) k_idx32(const void* __restrict__ idxp) {
    int i = blockIdx.x * TPB + threadIdx.x;
    if (i >= N_PTS * KNN) return;
    int v;
    if (g_idx64) v = (int)__ldcs(((const long long*)idxp) + i);
    else         v = __ldcs(((const int*)idxp) + i);
    __stcs(&g_idx[i], v);
}

// G0 = W1[:, :20]*feat + W1[:,20:]*pts, compact 20-float rows
__global__ void __launch_bounds__(TPB) k_prep(const float* __restrict__ pts,
                                              const float* __restrict__ feat,
                                              const float* __restrict__ W1) {
    __shared__ float sW[C * CIN3];
    for (int i = threadIdx.x; i < C * CIN3; i += TPB) sW[i] = W1[i];
    __syncthreads();
    int n = blockIdx.x * TPB + threadIdx.x;
    if (n >= N_PTS) return;
    float f[C];
    load20(f, &feat[n * C]);
    float p0 = pts[n*3], p1 = pts[n*3+1], p2 = pts[n*3+2];
    float G[C];
#pragma unroll
    for (int o = 0; o < C; o++) {
        const float* w = &sW[o * CIN3];
        float acc = fmaf(w[22], p2, fmaf(w[21], p1, w[20] * p0));
#pragma unroll
        for (int c = 0; c < C; c++) acc = fmaf(w[c], f[c], acc);
        G[o] = acc;
    }
    float4* q = (float4*)&g_G0[(size_t)n * RST];
#pragma unroll
    for (int i = 0; i < 5; i++) {
        float4 t;
        t.x = G[4*i]; t.y = G[4*i+1]; t.z = G[4*i+2]; t.w = G[4*i+3];
        q[i] = t;
    }
}

// BN1 stats over 9M of (G0[idx] - Wp*pts[n]); 8 lanes/point; batched loads
__global__ void __launch_bounds__(TPB, 6) k_stats(const float* __restrict__ pts,
                                                  const float* __restrict__ W1,
                                                  const float* __restrict__ g1,
                                                  const float* __restrict__ b1) {
    __shared__ float sWp[3][32];
    int tid = threadIdx.x;
    if (tid < 96) {
        int d = tid / 32, c = tid % 32;
        sWp[d][c] = (c < C) ? W1[c * CIN3 + 20 + d] : 0.f;
    }
    __syncthreads();
    uint64_t pol = evl_policy();
    int lane = tid & 31, warp = tid >> 5;
    int l = lane & 7, sub = lane >> 3;

    int p = blockIdx.x * PPBG + warp * 4 + sub;
    int jv = __ldcs(&g_idx[p * KNN + l]);
    int j8 = __ldcs(&g_idx[p * KNN + 8]);

    // issue all 9 gathers back-to-back
    float4 t[KNN];
#pragma unroll
    for (int k = 0; k < KNN; k++) {
        int j = (k < 8) ? __shfl_sync(FULLM, jv, k, 8) : j8;
        t[k] = make_float4(0.f, 0.f, 0.f, 0.f);
        if (l < 5) t[k] = ldg_evl(g_G0 + (size_t)j * RST + 4*l, pol);
    }

    float px = pts[p*3], py = pts[p*3+1], pz = pts[p*3+2];
    float pp[4];
#pragma unroll
    for (int i = 0; i < 4; i++) {
        int c = 4*l + i;
        pp[i] = fmaf(sWp[2][c], pz, fmaf(sWp[1][c], py, sWp[0][c] * px));
    }
    float s[4] = {0,0,0,0}, q[4] = {0,0,0,0};
#pragma unroll
    for (int k = 0; k < KNN; k++) {
        float d0 = t[k].x - pp[0], d1 = t[k].y - pp[1];
        float d2 = t[k].z - pp[2], d3 = t[k].w - pp[3];
        s[0] += d0; q[0] = fmaf(d0, d0, q[0]);
        s[1] += d1; q[1] = fmaf(d1, d1, q[1]);
        s[2] += d2; q[2] = fmaf(d2, d2, q[2]);
        s[3] += d3; q[3] = fmaf(d3, d3, q[3]);
    }
    if (l >= 5) {
#pragma unroll
        for (int i = 0; i < 4; i++) { s[i] = 0.f; q[i] = 0.f; }
    }
    lane_stats_store(s, q, blockIdx.x);
    fold_tail(NBLKG, g1, b1, 1.0f / (float)(N_PTS * KNN));
}

// first aggregation, 8 lanes/point, batched loads; v/wgt evict-first
__global__ void __launch_bounds__(TPB, 5) k_agg1(const float* __restrict__ pts,
                                                 const float* __restrict__ W1) {
    __shared__ float sWp[3][32];
    __shared__ float ssc[32], sbi[32];
    int tid = threadIdx.x;
    if (tid < 96) {
        int d = tid / 32, c = tid % 32;
        sWp[d][c] = (c < C) ? W1[c * CIN3 + 20 + d] : 0.f;
    }
    if (tid < 32) {
        ssc[tid] = (tid < C) ? g_scale[tid] : 0.f;
        sbi[tid] = (tid < C) ? g_bias[tid]  : 0.f;
    }
    __syncthreads();
    uint64_t pol = evl_policy();
    int lane = tid & 31, warp = tid >> 5;
    int l = lane & 7, sub = lane >> 3;

    int p = blockIdx.x * PPBG + warp * 4 + sub;
    int jv = __ldcs(&g_idx[p * KNN + l]);
    int j8 = __ldcs(&g_idx[p * KNN + 8]);

    float4 t[KNN];
#pragma unroll
    for (int k = 0; k < KNN; k++) {
        int j = (k < 8) ? __shfl_sync(FULLM, jv, k, 8) : j8;
        t[k] = make_float4(0.f, 0.f, 0.f, 0.f);
        if (l < 5) t[k] = ldg_evl(g_G0 + (size_t)j * RST + 4*l, pol);
    }

    float px = pts[p*3], py = pts[p*3+1], pz = pts[p*3+2];
    float sc[4], base[4];
#pragma unroll
    for (int i = 0; i < 4; i++) {
        int c = 4*l + i;
        float pp = fmaf(sWp[2][c], pz, fmaf(sWp[1][c], py, sWp[0][c] * px));
        sc[i]   = ssc[c];
        base[i] = fmaf(-ssc[c], pp, sbi[c]);
    }
    float x0[4];
    x0[0] = fmaf(sc[0], t[0].x, base[0]);
    x0[1] = fmaf(sc[1], t[0].y, base[1]);
    x0[2] = fmaf(sc[2], t[0].z, base[2]);
    x0[3] = fmaf(sc[3], t[0].w, base[3]);
    float wp = fmaf(x0[0], x0[0], fmaf(x0[1], x0[1],
               fmaf(x0[2], x0[2], x0[3] * x0[3])));
    float w0 = grp8_sum(wp);
    float v[4];
#pragma unroll
    for (int i = 0; i < 4; i++) v[i] = x0[i] * w0;
    float wsv = w0;
    float w8  = 0.f;
#pragma unroll
    for (int k = 1; k < KNN; k++) {
        float xk0 = fmaf(sc[0], t[k].x, base[0]);
        float xk1 = fmaf(sc[1], t[k].y, base[1]);
        float xk2 = fmaf(sc[2], t[k].z, base[2]);
        float xk3 = fmaf(sc[3], t[k].w, base[3]);
        float dp = fmaf(xk0, x0[0], fmaf(xk1, x0[1],
                   fmaf(xk2, x0[2], xk3 * x0[3])));
        float wk = grp8_sum(dp);
        v[0] = fmaf(xk0, wk, v[0]);
        v[1] = fmaf(xk1, wk, v[1]);
        v[2] = fmaf(xk2, wk, v[2]);
        v[3] = fmaf(xk3, wk, v[3]);
        if (l == k) wsv = wk;
        if (k == 8) w8 = wk;
    }
    __stcs(&g_wgt[p * KNN + l], wsv);
    if (l == 0) __stcs(&g_wgt[p * KNN + 8], w8);
    if (l < 5) {
        float4 o4;
        o4.x = v[0]; o4.y = v[1]; o4.z = v[2]; o4.w = v[3];
        __stcs((float4*)(g_v + (size_t)p * RST + 4*l), o4);
    }
}

// second aggregation: x2 = sum_k v[idx]*w ; batched loads; BN2 stats + fold
__global__ void __launch_bounds__(TPB, 5) k_agg2(const float* __restrict__ g2,
                                                 const float* __restrict__ b2) {
    int tid = threadIdx.x;
    uint64_t pol = evl_policy();
    int lane = tid & 31, warp = tid >> 5;
    int l = lane & 7, sub = lane >> 3;

    int p = blockIdx.x * PPBG + warp * 4 + sub;
    int jv = __ldcs(&g_idx[p * KNN + l]);
    int j8 = __ldcs(&g_idx[p * KNN + 8]);
    float wv = __ldcs(&g_wgt[p * KNN + l]);
    float w8 = __ldcs(&g_wgt[p * KNN + 8]);

    float4 t[KNN];
#pragma unroll
    for (int k = 0; k < KNN; k++) {
        int j = (k < 8) ? __shfl_sync(FULLM, jv, k, 8) : j8;
        t[k] = make_float4(0.f, 0.f, 0.f, 0.f);
        if (l < 5) t[k] = ldg_evl(g_v + (size_t)j * RST + 4*l, pol);
    }

    float acc[4] = {0,0,0,0};
#pragma unroll
    for (int k = 0; k < KNN; k++) {
        float wk = (k < 8) ? __shfl_sync(FULLM, wv, k, 8) : w8;
        acc[0] = fmaf(t[k].x, wk, acc[0]);
        acc[1] = fmaf(t[k].y, wk, acc[1]);
        acc[2] = fmaf(t[k].z, wk, acc[2]);
        acc[3] = fmaf(t[k].w, wk, acc[3]);
    }
    if (l < 5) {
        float4 o4;
        o4.x = acc[0]; o4.y = acc[1]; o4.z = acc[2]; o4.w = acc[3];
        __stcs((float4*)(g_x2 + (size_t)p * C + 4*l), o4);
    }
    float s[4], q[4];
#pragma unroll
    for (int i = 0; i < 4; i++) {
        s[i] = (l < 5) ? acc[i] : 0.f;
        q[i] = (l < 5) ? acc[i] * acc[i] : 0.f;
    }
    lane_stats_store(s, q, blockIdx.x);
    fold_tail(NBLKG, g2, b2, 1.0f / (float)N_PTS);
}

// refine stage 1: r = relu(bn2(x2)); h = Wr1 @ [r, feat] + br1; BN3 stats + fold
__global__ void __launch_bounds__(TPB) k_refine1(const float* __restrict__ feat,
                                                 const float* __restrict__ Wr1,
                                                 const float* __restrict__ br1,
                                                 const float* __restrict__ g3,
                                                 const float* __restrict__ b3) {
    __shared__ float sW[C * 40], sb[C], ssc[C], sbi[C];
    for (int i = threadIdx.x; i < C * 40; i += TPB) sW[i] = Wr1[i];
    if (threadIdx.x < C) {
        sb[threadIdx.x]  = br1[threadIdx.x];
        ssc[threadIdx.x] = g_scale[threadIdx.x];
        sbi[threadIdx.x] = g_bias[threadIdx.x];
    }
    __syncthreads();
    int n = blockIdx.x * TPB + threadIdx.x;
    float s[C], q[C];
#pragma unroll
    for (int o = 0; o < C; o++) { s[o] = 0.f; q[o] = 0.f; }
    if (n < N_PTS) {
        float r[40];
        const float4* xq = (const float4*)(g_x2 + (size_t)n * C);
#pragma unroll
        for (int i = 0; i < 5; i++) {
            float4 t = __ldcs(xq + i);
            r[4*i] = t.x; r[4*i+1] = t.y; r[4*i+2] = t.z; r[4*i+3] = t.w;
        }
#pragma unroll
        for (int c = 0; c < C; c++) r[c] = fmaxf(fmaf(r[c], ssc[c], sbi[c]), 0.f);
        load20(r + C, &feat[n * C]);
        float hh[C];
#pragma unroll
        for (int o = 0; o < C; o++) {
            const float* w = &sW[o * 40];
            float a = sb[o];
#pragma unroll
            for (int c = 0; c < 40; c++) a = fmaf(w[c], r[c], a);
            hh[o] = a; s[o] = a; q[o] = a * a;
        }
        float4* hq = (float4*)(g_h + (size_t)n * C);
#pragma unroll
        for (int i = 0; i < 5; i++) {
            float4 t;
            t.x = hh[4*i]; t.y = hh[4*i+1]; t.z = hh[4*i+2]; t.w = hh[4*i+3];
            __stcs(hq + i, t);
        }
    }
    stats_reduce_store(s, q, blockIdx.x);
    fold_tail(NBLKR, g3, b3, 1.0f / (float)N_PTS);
}

// output: out = Wr2 @ relu(bn3(h)) + br2
__global__ void __launch_bounds__(TPB) k_out(const float* __restrict__ Wr2,
                                             const float* __restrict__ br2,
                                             float* __restrict__ out) {
    __shared__ float sW[C * C], sb[C], ssc[C], sbi[C];
    for (int i = threadIdx.x; i < C * C; i += TPB) sW[i] = Wr2[i];
    if (threadIdx.x < C) {
        sb[threadIdx.x]  = br2[threadIdx.x];
        ssc[threadIdx.x] = g_scale[threadIdx.x];
        sbi[threadIdx.x] = g_bias[threadIdx.x];
    }
    __syncthreads();
    int n = blockIdx.x * TPB + threadIdx.x;
    if (n >= N_PTS) return;
    float r[C];
    const float4* hq = (const float4*)(g_h + (size_t)n * C);
#pragma unroll
    for (int i = 0; i < 5; i++) {
        float4 t = __ldcs(hq + i);
        r[4*i] = t.x; r[4*i+1] = t.y; r[4*i+2] = t.z; r[4*i+3] = t.w;
    }
#pragma unroll
    for (int c = 0; c < C; c++) r[c] = fmaxf(fmaf(r[c], ssc[c], sbi[c]), 0.f);
    float o_[C];
#pragma unroll
    for (int o = 0; o < C; o++) {
        const float* w = &sW[o * C];
        float a = sb[o];
#pragma unroll
        for (int c = 0; c < C; c++) a = fmaf(w[c], r[c], a);
        o_[o] = a;
    }
    float4* oq = (float4*)(out + (size_t)n * C);
#pragma unroll
    for (int i = 0; i < 5; i++) {
        float4 t;
        t.x = o_[4*i]; t.y = o_[4*i+1]; t.z = o_[4*i+2]; t.w = o_[4*i+3];
        __stcs(oq + i, t);
    }
}

// ---------------- launch ----------------------------------------------------
extern "C" void kernel_launch(void* const* d_in, const int* in_sizes, int n_in,
                              void* d_out, int out_size) {
    const float* pts  = (const float*)d_in[0];
    const float* feat = (const float*)d_in[1];
    const void*  idx  = d_in[2];
    const float* W1   = (const float*)d_in[3];
    const float* g1   = (const float*)d_in[4];
    const float* b1   = (const float*)d_in[5];
    const float* g2   = (const float*)d_in[6];
    const float* b2   = (const float*)d_in[7];
    const float* Wr1  = (const float*)d_in[8];
    const float* br1  = (const float*)d_in[9];
    const float* g3   = (const float*)d_in[10];
    const float* b3   = (const float*)d_in[11];
    const float* Wr2  = (const float*)d_in[12];
    const float* br2  = (const float*)d_in[13];
    float* out = (float*)d_out;

    k_detect<<<1, 32>>>(idx);
    k_idx32<<<(N_PTS * KNN + TPB - 1) / TPB, TPB>>>(idx);
    k_prep<<<NBLKR, TPB>>>(pts, feat, W1);

    // BN1 stats + in-kernel fold
    k_stats<<<NBLKG, TPB>>>(pts, W1, g1, b1);

    // aggregation passes (agg2 folds BN2)
    k_agg1<<<NBLKG, TPB>>>(pts, W1);
    k_agg2<<<NBLKG, TPB>>>(g2, b2);

    // refine linear 1 (folds BN3)
    k_refine1<<<NBLKR, TPB>>>(feat, Wr1, br1, g3, b3);

    // final linear
    k_out<<<NBLKR, TPB>>>(Wr2, br2, out);
}

// round 11
// speedup vs baseline: 1.5902x; 1.5902x over previous
#include <cuda_runtime.h>
#include <cuda_fp16.h>
#include <cstdint>

#define N_PTS  1000000
#define KNN    9
#define C      20
#define CIN3   23
#define TPB    256
#define RSH    24                               // halfs per padded row = 48B
#define PPBG   128                              // points per block (8 warps*8 pts*2 it)
#define NBLKG  ((N_PTS + PPBG - 1) / PPBG)      // 7813
#define NBLKR  ((N_PTS + TPB - 1) / TPB)        // 3907
#define PARTN  NBLKG
#define EPSV   1e-5f
#define FULLM  0xffffffffu

// ---------------- scratch (device globals; allocation-free) -----------------
__device__ __align__(16) __half g_G0h[(size_t)N_PTS * RSH];  // fp16 conv precompute (48MB)
__device__ __align__(16) __half g_vh [(size_t)N_PTS * RSH];  // fp16 first aggregation (48MB)
__device__ __align__(16) float  g_x2 [N_PTS * C];            // second aggregation (fp32)
__device__ __align__(16) float  g_h  [N_PTS * C];            // pre-BN3 linear output
__device__ __align__(16) int    g_idx[N_PTS * KNN];          // int32 index copy (36MB)
__device__ float g_wgt[N_PTS * KNN];
__device__ float g_part_t[40 * PARTN];
__device__ float g_scale[C];
__device__ float g_bias[C];
__device__ int   g_idx64;
__device__ int   g_arrive;

// ---------------- helpers ---------------------------------------------------
__device__ __forceinline__ void load20(float* r, const float* p) {
    const float4* q = (const float4*)p;
#pragma unroll
    for (int i = 0; i < 5; i++) {
        float4 t = q[i];
        r[4*i] = t.x; r[4*i+1] = t.y; r[4*i+2] = t.z; r[4*i+3] = t.w;
    }
}
__device__ __forceinline__ unsigned h2u(__half2 h) { return *(unsigned*)&h; }
__device__ __forceinline__ float2 u2f(unsigned u) { return __half22float2(*(__half2*)&u); }
// sum within 4-lane group
__device__ __forceinline__ float grp4_sum(float v) {
    v += __shfl_xor_sync(FULLM, v, 1);
    v += __shfl_xor_sync(FULLM, v, 2);
    return v;
}

// last-arriving block reduces g_part_t and folds BN into g_scale/g_bias
__device__ void fold_tail(int nblk, const float* __restrict__ g,
                          const float* __restrict__ b, float inv_count) {
    __shared__ int s_last;
    __threadfence();
    __syncthreads();
    if (threadIdx.x == 0) {
        int prev = atomicAdd(&g_arrive, 1);
        s_last = (prev == nblk - 1) ? 1 : 0;
    }
    __syncthreads();
    if (!s_last) return;
    __threadfence();
    int lane = threadIdx.x & 31, warp = threadIdx.x >> 5;
    __shared__ float tot[40];
#pragma unroll
    for (int si = 0; si < 5; si++) {
        int slot = warp + si * 8;
        const float* pp = g_part_t + slot * PARTN;
        float a0 = 0.f, a1 = 0.f, a2 = 0.f, a3 = 0.f;
        int i = lane;
        for (; i + 96 < nblk; i += 128) {
            a0 += pp[i]; a1 += pp[i+32]; a2 += pp[i+64]; a3 += pp[i+96];
        }
        for (; i < nblk; i += 32) a0 += pp[i];
        float a = (a0 + a1) + (a2 + a3);
#pragma unroll
        for (int off = 16; off > 0; off >>= 1) a += __shfl_xor_sync(FULLM, a, off);
        if (lane == 0) tot[slot] = a;
    }
    __syncthreads();
    if (threadIdx.x < C) {
        int o = threadIdx.x;
        float mean = tot[o] * inv_count;
        float var  = fmaf(-mean, mean, tot[20 + o] * inv_count);
        float x = var + EPSV;
        float r = rsqrtf(x);
        r = r * (1.5f - 0.5f * x * r * r);
        float sc = g[o] * r;
        g_scale[o] = sc;
        g_bias[o]  = b[o] - mean * sc;
    }
    if (threadIdx.x == 0) g_arrive = 0;
}

// 4-lane-group stats: lane l (=lane&3) holds channels 8l..8l+7 (pads zero)
__device__ __forceinline__ void lane_stats_store4(float* s, float* q, int blk) {
    int lane = threadIdx.x & 31, warp = threadIdx.x >> 5;
#pragma unroll
    for (int i = 0; i < 8; i++) {
        s[i] += __shfl_down_sync(FULLM, s[i], 16);
        s[i] += __shfl_down_sync(FULLM, s[i], 8);
        s[i] += __shfl_down_sync(FULLM, s[i], 4);
        q[i] += __shfl_down_sync(FULLM, q[i], 16);
        q[i] += __shfl_down_sync(FULLM, q[i], 8);
        q[i] += __shfl_down_sync(FULLM, q[i], 4);
    }
    __shared__ float sh[8][40];
    if (lane < 3) {
#pragma unroll
        for (int i = 0; i < 8; i++) {
            int c = 8 * lane + i;
            if (c < C) { sh[warp][c] = s[i]; sh[warp][20 + c] = q[i]; }
        }
    }
    __syncthreads();
    if (threadIdx.x < 40) {
        float a = 0.f;
#pragma unroll
        for (int w = 0; w < 8; w++) a += sh[w][threadIdx.x];
        g_part_t[threadIdx.x * PARTN + blk] = a;
    }
}

// per-thread stats (all 20 channels) -> block partials (refine kernel)
__device__ __forceinline__ void stats_reduce_store(float* s, float* q, int blk) {
#pragma unroll
    for (int o = 0; o < C; o++) {
#pragma unroll
        for (int off = 16; off > 0; off >>= 1) {
            s[o] += __shfl_down_sync(FULLM, s[o], off);
            q[o] += __shfl_down_sync(FULLM, q[o], off);
        }
    }
    __shared__ float sh[8][40];
    int warp = threadIdx.x >> 5, lane = threadIdx.x & 31;
    if (lane == 0) {
#pragma unroll
        for (int o = 0; o < C; o++) { sh[warp][o] = s[o]; sh[warp][20+o] = q[o]; }
    }
    __syncthreads();
    if (threadIdx.x < 40) {
        float a = 0.f;
#pragma unroll
        for (int w = 0; w < 8; w++) a += sh[w][threadIdx.x];
        g_part_t[threadIdx.x * PARTN + blk] = a;
    }
}

// ---------------- kernels ---------------------------------------------------

__global__ void k_detect(const void* idx) {
    if (threadIdx.x == 0) {
        const int* p = (const int*)idx;
        int odd_zero = 1;
        for (int i = 0; i < 64; i++)
            if (p[2 * i + 1] != 0) odd_zero = 0;
        g_idx64 = odd_zero;
    }
}

__global__ void __launch_bounds__(TPB) k_idx32(const void* __restrict__ idxp) {
    int i = blockIdx.x * TPB + threadIdx.x;
    if (i >= N_PTS * KNN) return;
    int v;
    if (g_idx64) v = (int)__ldcs(((const long long*)idxp) + i);
    else         v = __ldcs(((const int*)idxp) + i);
    __stcs(&g_idx[i], v);
}

// G0h = fp16(W1[:, :20]*feat + W1[:,20:]*pts), 24-half padded rows
__global__ void __launch_bounds__(TPB) k_prep(const float* __restrict__ pts,
                                              const float* __restrict__ feat,
                                              const float* __restrict__ W1) {
    __shared__ float sW[C * CIN3];
    for (int i = threadIdx.x; i < C * CIN3; i += TPB) sW[i] = W1[i];
    __syncthreads();
    int n = blockIdx.x * TPB + threadIdx.x;
    if (n >= N_PTS) return;
    float f[C];
    load20(f, &feat[n * C]);
    float p0 = pts[n*3], p1 = pts[n*3+1], p2 = pts[n*3+2];
    float G[C];
#pragma unroll
    for (int o = 0; o < C; o++) {
        const float* w = &sW[o * CIN3];
        float acc = fmaf(w[22], p2, fmaf(w[21], p1, w[20] * p0));
#pragma unroll
        for (int c = 0; c < C; c++) acc = fmaf(w[c], f[c], acc);
        G[o] = acc;
    }
    uint4 o0, o1, o2;
    o0.x = h2u(__floats2half2_rn(G[0],  G[1]));
    o0.y = h2u(__floats2half2_rn(G[2],  G[3]));
    o0.z = h2u(__floats2half2_rn(G[4],  G[5]));
    o0.w = h2u(__floats2half2_rn(G[6],  G[7]));
    o1.x = h2u(__floats2half2_rn(G[8],  G[9]));
    o1.y = h2u(__floats2half2_rn(G[10], G[11]));
    o1.z = h2u(__floats2half2_rn(G[12], G[13]));
    o1.w = h2u(__floats2half2_rn(G[14], G[15]));
    o2.x = h2u(__floats2half2_rn(G[16], G[17]));
    o2.y = h2u(__floats2half2_rn(G[18], G[19]));
    o2.z = 0u; o2.w = 0u;                      // pad channels 20..23 = 0
    uint4* q = (uint4*)(g_G0h + (size_t)n * RSH);
    q[0] = o0; q[1] = o1; q[2] = o2;
}

// BN1 stats over 9M of (G0[idx] - Wp*pts[n]); 4 lanes/point; fused fold
__global__ void __launch_bounds__(TPB) k_stats(const float* __restrict__ pts,
                                               const float* __restrict__ W1,
                                               const float* __restrict__ g1,
                                               const float* __restrict__ b1) {
    __shared__ float sWp[3][32];
    int tid = threadIdx.x;
    if (tid < 96) {
        int d = tid / 32, c = tid % 32;
        sWp[d][c] = (c < C) ? W1[c * CIN3 + 20 + d] : 0.f;
    }
    __syncthreads();
    int lane = tid & 31, warp = tid >> 5;
    int l = lane & 3, grp = lane >> 2;

    float s[8], q[8];
#pragma unroll
    for (int i = 0; i < 8; i++) { s[i] = 0.f; q[i] = 0.f; }

#pragma unroll 1
    for (int it = 0; it < 2; it++) {
        int p = blockIdx.x * PPBG + it * 64 + warp * 8 + grp;
        bool valid = p < N_PTS;
        int pc = valid ? p : N_PTS - 1;
        float vf = valid ? 1.f : 0.f;
        int iA = __ldcs(&g_idx[pc * KNN + l]);
        int iB = __ldcs(&g_idx[pc * KNN + 4 + l]);
        int i8 = __ldcs(&g_idx[pc * KNN + 8]);

        uint4 t[KNN];
#pragma unroll
        for (int k = 0; k < KNN; k++) {
            int j = (k < 4) ? __shfl_sync(FULLM, iA, k, 4)
                  : (k < 8) ? __shfl_sync(FULLM, iB, k - 4, 4) : i8;
            t[k] = make_uint4(0u, 0u, 0u, 0u);
            if (l < 3) t[k] = *(const uint4*)(g_G0h + (size_t)j * RSH + l * 8);
        }

        float px = pts[pc*3], py = pts[pc*3+1], pz = pts[pc*3+2];
        float pp[8];
#pragma unroll
        for (int i = 0; i < 8; i++) {
            int c = 8 * l + i;
            float w0 = (c < 32) ? sWp[0][c & 31] : 0.f;   // l=3 -> c>=24: weights are 0 anyway for c>=20
            float w1 = (c < 32) ? sWp[1][c & 31] : 0.f;
            float w2 = (c < 32) ? sWp[2][c & 31] : 0.f;
            pp[i] = (l < 3) ? fmaf(w2, pz, fmaf(w1, py, w0 * px)) : 0.f;
        }
#pragma unroll
        for (int k = 0; k < KNN; k++) {
            float2 f0 = u2f(t[k].x), f1 = u2f(t[k].y);
            float2 f2 = u2f(t[k].z), f3 = u2f(t[k].w);
            float d0 = (f0.x - pp[0]) * vf, d1 = (f0.y - pp[1]) * vf;
            float d2 = (f1.x - pp[2]) * vf, d3 = (f1.y - pp[3]) * vf;
            float d4 = (f2.x - pp[4]) * vf, d5 = (f2.y - pp[5]) * vf;
            float d6 = (f3.x - pp[6]) * vf, d7 = (f3.y - pp[7]) * vf;
            s[0] += d0; q[0] = fmaf(d0, d0, q[0]);
            s[1] += d1; q[1] = fmaf(d1, d1, q[1]);
            s[2] += d2; q[2] = fmaf(d2, d2, q[2]);
            s[3] += d3; q[3] = fmaf(d3, d3, q[3]);
            s[4] += d4; q[4] = fmaf(d4, d4, q[4]);
            s[5] += d5; q[5] = fmaf(d5, d5, q[5]);
            s[6] += d6; q[6] = fmaf(d6, d6, q[6]);
            s[7] += d7; q[7] = fmaf(d7, d7, q[7]);
        }
    }
    lane_stats_store4(s, q, blockIdx.x);
    fold_tail(NBLKG, g1, b1, 1.0f / (float)(N_PTS * KNN));
}

// first aggregation, 4 lanes/point: x_k = s*G0[idx] + (t - s*Wp*pts[n]);
// w_k = x_k . x_0 ; v = sum_k x_k*w_k (stored fp16) ; store w_k
__global__ void __launch_bounds__(TPB) k_agg1(const float* __restrict__ pts,
                                              const float* __restrict__ W1) {
    __shared__ float sWp[3][32];
    __shared__ float ssc[32], sbi[32];
    int tid = threadIdx.x;
    if (tid < 96) {
        int d = tid / 32, c = tid % 32;
        sWp[d][c] = (c < C) ? W1[c * CIN3 + 20 + d] : 0.f;
    }
    if (tid < 32) {
        ssc[tid] = (tid < C) ? g_scale[tid] : 0.f;
        sbi[tid] = (tid < C) ? g_bias[tid]  : 0.f;
    }
    __syncthreads();
    int lane = tid & 31, warp = tid >> 5;
    int l = lane & 3, grp = lane >> 2;

#pragma unroll 1
    for (int it = 0; it < 2; it++) {
        int p = blockIdx.x * PPBG + it * 64 + warp * 8 + grp;
        bool valid = p < N_PTS;
        int pc = valid ? p : N_PTS - 1;
        int iA = __ldcs(&g_idx[pc * KNN + l]);
        int iB = __ldcs(&g_idx[pc * KNN + 4 + l]);
        int i8 = __ldcs(&g_idx[pc * KNN + 8]);

        uint4 t[KNN];
#pragma unroll
        for (int k = 0; k < KNN; k++) {
            int j = (k < 4) ? __shfl_sync(FULLM, iA, k, 4)
                  : (k < 8) ? __shfl_sync(FULLM, iB, k - 4, 4) : i8;
            t[k] = make_uint4(0u, 0u, 0u, 0u);
            if (l < 3) t[k] = *(const uint4*)(g_G0h + (size_t)j * RSH + l * 8);
        }

        float px = pts[pc*3], py = pts[pc*3+1], pz = pts[pc*3+2];
        float sc[8], base[8];
#pragma unroll
        for (int i = 0; i < 8; i++) {
            int c = 8 * l + i;
            if (l < 3) {
                float pp = fmaf(sWp[2][c & 31], pz,
                           fmaf(sWp[1][c & 31], py, sWp[0][c & 31] * px));
                sc[i]   = ssc[c & 31];
                base[i] = fmaf(-ssc[c & 31], pp, sbi[c & 31]);
            } else { sc[i] = 0.f; base[i] = 0.f; }
        }
        // neighbor 0
        float x0[8];
        {
            float2 f0 = u2f(t[0].x), f1 = u2f(t[0].y);
            float2 f2 = u2f(t[0].z), f3 = u2f(t[0].w);
            x0[0] = fmaf(sc[0], f0.x, base[0]); x0[1] = fmaf(sc[1], f0.y, base[1]);
            x0[2] = fmaf(sc[2], f1.x, base[2]); x0[3] = fmaf(sc[3], f1.y, base[3]);
            x0[4] = fmaf(sc[4], f2.x, base[4]); x0[5] = fmaf(sc[5], f2.y, base[5]);
            x0[6] = fmaf(sc[6], f3.x, base[6]); x0[7] = fmaf(sc[7], f3.y, base[7]);
        }
        float wp = 0.f;
#pragma unroll
        for (int i = 0; i < 8; i++) wp = fmaf(x0[i], x0[i], wp);
        float w0 = grp4_sum(wp);
        float v[8];
#pragma unroll
        for (int i = 0; i < 8; i++) v[i] = x0[i] * w0;
        float wA = (l == 0) ? w0 : 0.f;
        float wB = 0.f, w8 = 0.f;
#pragma unroll
        for (int k = 1; k < KNN; k++) {
            float2 f0 = u2f(t[k].x), f1 = u2f(t[k].y);
            float2 f2 = u2f(t[k].z), f3 = u2f(t[k].w);
            float xk[8];
            xk[0] = fmaf(sc[0], f0.x, base[0]); xk[1] = fmaf(sc[1], f0.y, base[1]);
            xk[2] = fmaf(sc[2], f1.x, base[2]); xk[3] = fmaf(sc[3], f1.y, base[3]);
            xk[4] = fmaf(sc[4], f2.x, base[4]); xk[5] = fmaf(sc[5], f2.y, base[5]);
            xk[6] = fmaf(sc[6], f3.x, base[6]); xk[7] = fmaf(sc[7], f3.y, base[7]);
            float dp = 0.f;
#pragma unroll
            for (int i = 0; i < 8; i++) dp = fmaf(xk[i], x0[i], dp);
            float wk = grp4_sum(dp);
#pragma unroll
            for (int i = 0; i < 8; i++) v[i] = fmaf(xk[i], wk, v[i]);
            if (k < 4)      { if (l == k)     wA = wk; }
            else if (k < 8) { if (l == k - 4) wB = wk; }
            else            w8 = wk;
        }
        if (valid) {
            g_wgt[pc * KNN + l]     = wA;
            g_wgt[pc * KNN + 4 + l] = wB;
            if (l == 0) g_wgt[pc * KNN + 8] = w8;
            if (l < 3) {
                uint4 o4;
                o4.x = h2u(__floats2half2_rn(v[0], v[1]));
                o4.y = h2u(__floats2half2_rn(v[2], v[3]));
                o4.z = h2u(__floats2half2_rn(v[4], v[5]));
                o4.w = h2u(__floats2half2_rn(v[6], v[7]));
                *(uint4*)(g_vh + (size_t)pc * RSH + l * 8) = o4;
            }
        }
    }
}

// second aggregation: x2 = sum_k v[idx]*w ; fused BN2 stats + fold
__global__ void __launch_bounds__(TPB) k_agg2(const float* __restrict__ g2,
                                              const float* __restrict__ b2) {
    int tid = threadIdx.x;
    int lane = tid & 31, warp = tid >> 5;
    int l = lane & 3, grp = lane >> 2;

    float s[8], q[8];
#pragma unroll
    for (int i = 0; i < 8; i++) { s[i] = 0.f; q[i] = 0.f; }

#pragma unroll 1
    for (int it = 0; it < 2; it++) {
        int p = blockIdx.x * PPBG + it * 64 + warp * 8 + grp;
        bool valid = p < N_PTS;
        int pc = valid ? p : N_PTS - 1;
        int iA = __ldcs(&g_idx[pc * KNN + l]);
        int iB = __ldcs(&g_idx[pc * KNN + 4 + l]);
        int i8 = __ldcs(&g_idx[pc * KNN + 8]);
        float wAv = __ldcs(&g_wgt[pc * KNN + l]);
        float wBv = __ldcs(&g_wgt[pc * KNN + 4 + l]);
        float w8  = __ldcs(&g_wgt[pc * KNN + 8]);

        uint4 t[KNN];
#pragma unroll
        for (int k = 0; k < KNN; k++) {
            int j = (k < 4) ? __shfl_sync(FULLM, iA, k, 4)
                  : (k < 8) ? __shfl_sync(FULLM, iB, k - 4, 4) : i8;
            t[k] = make_uint4(0u, 0u, 0u, 0u);
            if (l < 3) t[k] = *(const uint4*)(g_vh + (size_t)j * RSH + l * 8);
        }

        float acc[8];
#pragma unroll
        for (int i = 0; i < 8; i++) acc[i] = 0.f;
#pragma unroll
        for (int k = 0; k < KNN; k++) {
            float wk = (k < 4) ? __shfl_sync(FULLM, wAv, k, 4)
                     : (k < 8) ? __shfl_sync(FULLM, wBv, k - 4, 4) : w8;
            float2 f0 = u2f(t[k].x), f1 = u2f(t[k].y);
            float2 f2 = u2f(t[k].z), f3 = u2f(t[k].w);
            acc[0] = fmaf(f0.x, wk, acc[0]); acc[1] = fmaf(f0.y, wk, acc[1]);
            acc[2] = fmaf(f1.x, wk, acc[2]); acc[3] = fmaf(f1.y, wk, acc[3]);
            acc[4] = fmaf(f2.x, wk, acc[4]); acc[5] = fmaf(f2.y, wk, acc[5]);
            acc[6] = fmaf(f3.x, wk, acc[6]); acc[7] = fmaf(f3.y, wk, acc[7]);
        }
        if (valid && l < 3) {
            float4 a;
            a.x = acc[0]; a.y = acc[1]; a.z = acc[2]; a.w = acc[3];
            __stcs((float4*)(g_x2 + (size_t)pc * C + 8 * l), a);
            if (l < 2) {
                float4 b;
                b.x = acc[4]; b.y = acc[5]; b.z = acc[6]; b.w = acc[7];
                __stcs((float4*)(g_x2 + (size_t)pc * C + 8 * l + 4), b);
            }
        }
        float vf = valid ? 1.f : 0.f;
#pragma unroll
        for (int i = 0; i < 8; i++) {
            float a = acc[i] * vf;
            s[i] += a; q[i] = fmaf(a, a, q[i]);
        }
    }
    lane_stats_store4(s, q, blockIdx.x);
    fold_tail(NBLKG, g2, b2, 1.0f / (float)N_PTS);
}

// refine stage 1: r = relu(bn2(x2)); h = Wr1 @ [r, feat] + br1; BN3 stats + fold
__global__ void __launch_bounds__(TPB) k_refine1(const float* __restrict__ feat,
                                                 const float* __restrict__ Wr1,
                                                 const float* __restrict__ br1,
                                                 const float* __restrict__ g3,
                                                 const float* __restrict__ b3) {
    __shared__ float sW[C * 40], sb[C], ssc[C], sbi[C];
    for (int i = threadIdx.x; i < C * 40; i += TPB) sW[i] = Wr1[i];
    if (threadIdx.x < C) {
        sb[threadIdx.x]  = br1[threadIdx.x];
        ssc[threadIdx.x] = g_scale[threadIdx.x];
        sbi[threadIdx.x] = g_bias[threadIdx.x];
    }
    __syncthreads();
    int n = blockIdx.x * TPB + threadIdx.x;
    float s[C], q[C];
#pragma unroll
    for (int o = 0; o < C; o++) { s[o] = 0.f; q[o] = 0.f; }
    if (n < N_PTS) {
        float r[40];
        const float4* xq = (const float4*)(g_x2 + (size_t)n * C);
#pragma unroll
        for (int i = 0; i < 5; i++) {
            float4 t = __ldcs(xq + i);
            r[4*i] = t.x; r[4*i+1] = t.y; r[4*i+2] = t.z; r[4*i+3] = t.w;
        }
#pragma unroll
        for (int c = 0; c < C; c++) r[c] = fmaxf(fmaf(r[c], ssc[c], sbi[c]), 0.f);
        load20(r + C, &feat[n * C]);
        float hh[C];
#pragma unroll
        for (int o = 0; o < C; o++) {
            const float* w = &sW[o * 40];
            float a = sb[o];
#pragma unroll
            for (int c = 0; c < 40; c++) a = fmaf(w[c], r[c], a);
            hh[o] = a; s[o] = a; q[o] = a * a;
        }
        float4* hq = (float4*)(g_h + (size_t)n * C);
#pragma unroll
        for (int i = 0; i < 5; i++) {
            float4 t;
            t.x = hh[4*i]; t.y = hh[4*i+1]; t.z = hh[4*i+2]; t.w = hh[4*i+3];
            __stcs(hq + i, t);
        }
    }
    stats_reduce_store(s, q, blockIdx.x);
    fold_tail(NBLKR, g3, b3, 1.0f / (float)N_PTS);
}

// output: out = Wr2 @ relu(bn3(h)) + br2
__global__ void __launch_bounds__(TPB) k_out(const float* __restrict__ Wr2,
                                             const float* __restrict__ br2,
                                             float* __restrict__ out) {
    __shared__ float sW[C * C], sb[C], ssc[C], sbi[C];
    for (int i = threadIdx.x; i < C * C; i += TPB) sW[i] = Wr2[i];
    if (threadIdx.x < C) {
        sb[threadIdx.x]  = br2[threadIdx.x];
        ssc[threadIdx.x] = g_scale[threadIdx.x];
        sbi[threadIdx.x] = g_bias[threadIdx.x];
    }
    __syncthreads();
    int n = blockIdx.x * TPB + threadIdx.x;
    if (n >= N_PTS) return;
    float r[C];
    const float4* hq = (const float4*)(g_h + (size_t)n * C);
#pragma unroll
    for (int i = 0; i < 5; i++) {
        float4 t = __ldcs(hq + i);
        r[4*i] = t.x; r[4*i+1] = t.y; r[4*i+2] = t.z; r[4*i+3] = t.w;
    }
#pragma unroll
    for (int c = 0; c < C; c++) r[c] = fmaxf(fmaf(r[c], ssc[c], sbi[c]), 0.f);
    float o_[C];
#pragma unroll
    for (int o = 0; o < C; o++) {
        const float* w = &sW[o * C];
        float a = sb[o];
#pragma unroll
        for (int c = 0; c < C; c++) a = fmaf(w[c], r[c], a);
        o_[o] = a;
    }
    float4* oq = (float4*)(out + (size_t)n * C);
#pragma unroll
    for (int i = 0; i < 5; i++) {
        float4 t;
        t.x = o_[4*i]; t.y = o_[4*i+1]; t.z = o_[4*i+2]; t.w = o_[4*i+3];
        __stcs(oq + i, t);
    }
}

// ---------------- launch ----------------------------------------------------
extern "C" void kernel_launch(void* const* d_in, const int* in_sizes, int n_in,
                              void* d_out, int out_size) {
    const float* pts  = (const float*)d_in[0];
    const float* feat = (const float*)d_in[1];
    const void*  idx  = d_in[2];
    const float* W1   = (const float*)d_in[3];
    const float* g1   = (const float*)d_in[4];
    const float* b1   = (const float*)d_in[5];
    const float* g2   = (const float*)d_in[6];
    const float* b2   = (const float*)d_in[7];
    const float* Wr1  = (const float*)d_in[8];
    const float* br1  = (const float*)d_in[9];
    const float* g3   = (const float*)d_in[10];
    const float* b3   = (const float*)d_in[11];
    const float* Wr2  = (const float*)d_in[12];
    const float* br2  = (const float*)d_in[13];
    float* out = (float*)d_out;

    k_detect<<<1, 32>>>(idx);
    k_idx32<<<(N_PTS * KNN + TPB - 1) / TPB, TPB>>>(idx);
    k_prep<<<NBLKR, TPB>>>(pts, feat, W1);

    // BN1 stats + in-kernel fold
    k_stats<<<NBLKG, TPB>>>(pts, W1, g1, b1);

    // aggregation passes (agg2 folds BN2)
    k_agg1<<<NBLKG, TPB>>>(pts, W1);
    k_agg2<<<NBLKG, TPB>>>(g2, b2);

    // refine linear 1 (folds BN3)
    k_refine1<<<NBLKR, TPB>>>(feat, Wr1, br1, g3, b3);

    // final linear
    k_out<<<NBLKR, TPB>>>(Wr2, br2, out);
}